// round 2
// baseline (speedup 1.0000x reference)
#include <cuda_runtime.h>

// Problem constants
#define BB    64      // batch
#define TT    64      // timesteps
#define HH    1024    // hidden
#define EE    512     // embed
#define SS    128     // source len
#define VDIM  1024    // values size
#define NGATE 4096    // 4*H
#define KS_G  8       // gates K-splits   (chunk 256, K=2048)
#define KS_Q  16      // q     K-splits   (chunk 64,  K=1024)
#define KS_P  32      // proj  K-splits   (chunk 64,  K=2048)

// ---------- device scratch (static: no allocation allowed) ----------
__device__ float d_gpart[KS_G * BB * NGATE];   // 8 MB   gates partials [s][b][row]
__device__ float d_qpart[KS_Q * BB * VDIM];    // 4 MB   q partials
__device__ float d_ppart[KS_P * BB * EE];      // 4 MB   proj partials
__device__ float d_inp0 [BB * HH];             // layer0 input  = cat(emb, out_prev)
__device__ float d_h    [2 * BB * HH];         // LSTM hidden (both layers)
__device__ float d_c    [2 * BB * HH];         // LSTM cell
__device__ float d_att  [BB * VDIM];           // attended context
__device__ float d_ofeed[BB * EE];             // previous output (input feed)

// ---------- prep: build layer-0 input [b][0:512]=emb[tgt], [512:1024]=out_prev ----------
__global__ __launch_bounds__(256) void prep_kernel(
    const int* __restrict__ tgt, const float* __restrict__ emb, int t)
{
    int b = blockIdx.x, tid = threadIdx.x;
    int tok = tgt[t * BB + b];
    float4 v;
    if (tid < 128) v = ((const float4*)(emb + (long)tok * EE))[tid];
    else           v = ((const float4*)(d_ofeed + b * EE))[tid - 128];
    ((float4*)(d_inp0 + b * HH))[tid] = v;
}

// ---------- split-K partial GEMM, 256 rows x 64 batch per block ----------
// Cpart[ks][b][rowsTot] += sum_{k in chunk} W[row][k] * A[b][k]
// A region: k<1024 -> A0, else A1 (both stride 1024). W region: same split (strideW param).
__global__ __launch_bounds__(256) void gemm256_kernel(
    const float* __restrict__ A0, const float* __restrict__ A1,
    const float* __restrict__ W0, const float* __restrict__ W1,
    int strideW, int rowsTot, float* __restrict__ Cpart)
{
    __shared__ __align__(16) float Ws[16][256];
    __shared__ __align__(16) float As[16][64];

    const int row0  = blockIdx.x * 256;
    const int kbase = blockIdx.y * 256;          // 256 = KCHUNK
    const float* A = (kbase < 1024) ? A0 : A1;
    const float* W = (kbase < 1024) ? W0 : W1;
    const int kofs = (kbase < 1024) ? kbase : kbase - 1024;

    const int tid  = threadIdx.x;
    const int trow = tid & 31;          // row group (x4, two groups 128 apart)
    const int tcol = tid >> 5;          // batch group (x8)
    const int lw_kq = tid & 3,  lw_r = tid >> 2;   // W loader
    const int la_b  = tid & 63, la_kq = tid >> 6;  // A loader

    float acc[8][8];
    #pragma unroll
    for (int i = 0; i < 8; i++)
        #pragma unroll
        for (int j = 0; j < 8; j++) acc[i][j] = 0.f;

    for (int kt = 0; kt < 16; kt++) {
        const int kk0 = kofs + kt * 16;
        // load W tile 256x16 (transposed into smem)
        #pragma unroll
        for (int i = 0; i < 4; i++) {
            int r = lw_r + 64 * i;
            float4 w4 = *(const float4*)&W[(long)(row0 + r) * strideW + kk0 + lw_kq * 4];
            Ws[lw_kq * 4 + 0][r] = w4.x; Ws[lw_kq * 4 + 1][r] = w4.y;
            Ws[lw_kq * 4 + 2][r] = w4.z; Ws[lw_kq * 4 + 3][r] = w4.w;
        }
        // load A tile 64x16
        {
            float4 a4 = *(const float4*)&A[la_b * 1024 + kk0 + la_kq * 4];
            As[la_kq * 4 + 0][la_b] = a4.x; As[la_kq * 4 + 1][la_b] = a4.y;
            As[la_kq * 4 + 2][la_b] = a4.z; As[la_kq * 4 + 3][la_b] = a4.w;
        }
        __syncthreads();
        #pragma unroll
        for (int kk = 0; kk < 16; kk++) {
            float4 w0 = *(const float4*)&Ws[kk][trow * 4];
            float4 w1v = *(const float4*)&Ws[kk][128 + trow * 4];
            float4 a0 = *(const float4*)&As[kk][tcol * 8];
            float4 a1v = *(const float4*)&As[kk][tcol * 8 + 4];
            float wr[8] = {w0.x, w0.y, w0.z, w0.w, w1v.x, w1v.y, w1v.z, w1v.w};
            float ab[8] = {a0.x, a0.y, a0.z, a0.w, a1v.x, a1v.y, a1v.z, a1v.w};
            #pragma unroll
            for (int i = 0; i < 8; i++)
                #pragma unroll
                for (int j = 0; j < 8; j++) acc[i][j] += wr[i] * ab[j];
        }
        __syncthreads();
    }
    // store partials: [s][b][row]
    #pragma unroll
    for (int g = 0; g < 2; g++)
        #pragma unroll
        for (int j = 0; j < 8; j++) {
            int b = tcol * 8 + j;
            float4 v = {acc[g * 4 + 0][j], acc[g * 4 + 1][j], acc[g * 4 + 2][j], acc[g * 4 + 3][j]};
            *(float4*)&Cpart[(long)(blockIdx.y * BB + b) * rowsTot + row0 + g * 128 + trow * 4] = v;
        }
}

// ---------- split-K partial GEMM, 128 rows x 64 batch, KCHUNK=64 (for q and proj) ----------
__global__ __launch_bounds__(256) void gemm128_kernel(
    const float* __restrict__ A0, const float* __restrict__ A1,
    const float* __restrict__ W0, const float* __restrict__ W1,
    int strideW, int rowsTot, float* __restrict__ Cpart)
{
    __shared__ __align__(16) float Ws[16][128];
    __shared__ __align__(16) float As[16][64];

    const int row0  = blockIdx.x * 128;
    const int kbase = blockIdx.y * 64;
    const float* A = (kbase < 1024) ? A0 : A1;
    const float* W = (kbase < 1024) ? W0 : W1;
    const int kofs = (kbase < 1024) ? kbase : kbase - 1024;

    const int tid  = threadIdx.x;
    const int trow = tid & 31;
    const int tcol = tid >> 5;
    const int lw_kq = tid & 3,  lw_r = tid >> 2;
    const int la_b  = tid & 63, la_kq = tid >> 6;

    float acc[4][8];
    #pragma unroll
    for (int i = 0; i < 4; i++)
        #pragma unroll
        for (int j = 0; j < 8; j++) acc[i][j] = 0.f;

    for (int kt = 0; kt < 4; kt++) {
        const int kk0 = kofs + kt * 16;
        #pragma unroll
        for (int i = 0; i < 2; i++) {
            int r = lw_r + 64 * i;
            float4 w4 = *(const float4*)&W[(long)(row0 + r) * strideW + kk0 + lw_kq * 4];
            Ws[lw_kq * 4 + 0][r] = w4.x; Ws[lw_kq * 4 + 1][r] = w4.y;
            Ws[lw_kq * 4 + 2][r] = w4.z; Ws[lw_kq * 4 + 3][r] = w4.w;
        }
        {
            float4 a4 = *(const float4*)&A[la_b * 1024 + kk0 + la_kq * 4];
            As[la_kq * 4 + 0][la_b] = a4.x; As[la_kq * 4 + 1][la_b] = a4.y;
            As[la_kq * 4 + 2][la_b] = a4.z; As[la_kq * 4 + 3][la_b] = a4.w;
        }
        __syncthreads();
        #pragma unroll
        for (int kk = 0; kk < 16; kk++) {
            float4 w0 = *(const float4*)&Ws[kk][trow * 4];
            float4 a0 = *(const float4*)&As[kk][tcol * 8];
            float4 a1v = *(const float4*)&As[kk][tcol * 8 + 4];
            float wr[4] = {w0.x, w0.y, w0.z, w0.w};
            float ab[8] = {a0.x, a0.y, a0.z, a0.w, a1v.x, a1v.y, a1v.z, a1v.w};
            #pragma unroll
            for (int i = 0; i < 4; i++)
                #pragma unroll
                for (int j = 0; j < 8; j++) acc[i][j] += wr[i] * ab[j];
        }
        __syncthreads();
    }
    #pragma unroll
    for (int j = 0; j < 8; j++) {
        int b = tcol * 8 + j;
        float4 v = {acc[0][j], acc[1][j], acc[2][j], acc[3][j]};
        *(float4*)&Cpart[(long)(blockIdx.y * BB + b) * rowsTot + row0 + trow * 4] = v;
    }
}

// ---------- LSTM cell: reduce gate partials + bias + activations -> h,c (in place) ----------
__global__ __launch_bounds__(256) void cell_kernel(
    const float* __restrict__ bih, const float* __restrict__ bhh,
    float* __restrict__ h, float* __restrict__ c)
{
    int idx = blockIdx.x * 256 + threadIdx.x;   // 0..65535 = b*1024+hh
    int b = idx >> 10, hh = idx & 1023;
    float g[4];
    #pragma unroll
    for (int gi = 0; gi < 4; gi++) {
        int base = gi * 1024 + hh;
        float acc = bih[base] + bhh[base];
        #pragma unroll
        for (int s = 0; s < KS_G; s++) acc += d_gpart[(long)(s * BB + b) * NGATE + base];
        g[gi] = acc;
    }
    float i_ = 1.f / (1.f + expf(-g[0]));
    float f_ = 1.f / (1.f + expf(-g[1]));
    float gg = tanhf(g[2]);
    float o_ = 1.f / (1.f + expf(-g[3]));
    float cn = f_ * c[idx] + i_ * gg;
    c[idx] = cn;
    h[idx] = o_ * tanhf(cn);
}

// ---------- attention: reduce q partials, scores, softmax, attended (one block per b) ----------
__global__ __launch_bounds__(256) void attn_kernel(
    const float* __restrict__ henc, const float* __restrict__ b1)
{
    __shared__ __align__(16) float qv[VDIM];
    __shared__ float sc[SS];
    int b = blockIdx.x, tid = threadIdx.x;

    // reduce q partials + bias
    for (int v = tid; v < VDIM; v += 256) {
        float acc = b1[v];
        #pragma unroll
        for (int s = 0; s < KS_Q; s++) acc += d_qpart[(long)(s * BB + b) * VDIM + v];
        qv[v] = acc;
    }
    __syncthreads();

    // scores: 8 warps x 16 scores, warp-dot over V=1024
    int w = tid >> 5, l = tid & 31;
    const float4* hb = (const float4*)(henc + (long)b * SS * VDIM);
    const float4* q4 = (const float4*)qv;
    for (int i = 0; i < 16; i++) {
        int s = w * 16 + i;
        const float4* hr = hb + s * 256;
        float acc = 0.f;
        #pragma unroll
        for (int j = 0; j < 8; j++) {
            float4 qq = q4[l + j * 32];
            float4 hv = hr[l + j * 32];
            acc += qq.x * hv.x + qq.y * hv.y + qq.z * hv.z + qq.w * hv.w;
        }
        #pragma unroll
        for (int off = 16; off; off >>= 1) acc += __shfl_xor_sync(~0u, acc, off);
        if (l == 0) sc[s] = acc;
    }
    __syncthreads();

    // softmax over S=128 (warp 0)
    if (w == 0) {
        float v0 = sc[l], v1 = sc[l + 32], v2 = sc[l + 64], v3 = sc[l + 96];
        float m = fmaxf(fmaxf(v0, v1), fmaxf(v2, v3));
        #pragma unroll
        for (int off = 16; off; off >>= 1) m = fmaxf(m, __shfl_xor_sync(~0u, m, off));
        float e0 = expf(v0 - m), e1 = expf(v1 - m), e2 = expf(v2 - m), e3 = expf(v3 - m);
        float sum = e0 + e1 + e2 + e3;
        #pragma unroll
        for (int off = 16; off; off >>= 1) sum += __shfl_xor_sync(~0u, sum, off);
        float inv = 1.f / sum;
        sc[l] = e0 * inv; sc[l + 32] = e1 * inv; sc[l + 64] = e2 * inv; sc[l + 96] = e3 * inv;
    }
    __syncthreads();

    // attended = probs @ h_enc[b]
    float4 acc = {0.f, 0.f, 0.f, 0.f};
    #pragma unroll 4
    for (int s = 0; s < SS; s++) {
        float p = sc[s];
        float4 hv = hb[s * 256 + tid];
        acc.x += p * hv.x; acc.y += p * hv.y; acc.z += p * hv.z; acc.w += p * hv.w;
    }
    ((float4*)(d_att + b * VDIM))[tid] = acc;
}

// ---------- output projection finish: reduce + bias + tanh, write output + feedback ----------
__global__ __launch_bounds__(256) void projfinish_kernel(
    const float* __restrict__ b2, float* __restrict__ out, int t)
{
    int idx = blockIdx.x * 256 + threadIdx.x;   // 0..32767 = b*512+e
    int b = idx >> 9, e = idx & 511;
    float acc = b2[e];
    #pragma unroll
    for (int s = 0; s < KS_P; s++) acc += d_ppart[(long)(s * BB + b) * EE + e];
    float o = tanhf(acc);
    d_ofeed[idx] = o;
    out[(long)(b * TT + t) * EE + e] = o;
}

// ---------- launcher ----------
extern "C" void kernel_launch(void* const* d_in, const int* in_sizes, int n_in,
                              void* d_out, int out_size)
{
    const int*   tgt  = (const int*)d_in[0];
    const float* henc = (const float*)d_in[1];
    const float* emb  = (const float*)d_in[2];
    const float* out0 = (const float*)d_in[3];
    const float* hid0 = (const float*)d_in[4];
    const float* Wih  = (const float*)d_in[5];
    const float* Whh  = (const float*)d_in[6];
    const float* bih  = (const float*)d_in[7];
    const float* bhh  = (const float*)d_in[8];
    const float* W1   = (const float*)d_in[9];
    const float* b1   = (const float*)d_in[10];
    const float* W2   = (const float*)d_in[11];
    const float* b2   = (const float*)d_in[12];
    float* out = (float*)d_out;

    float *ph, *pc, *pof, *pin0, *pg, *pq, *pp, *patt;
    cudaGetSymbolAddress((void**)&ph,   d_h);
    cudaGetSymbolAddress((void**)&pc,   d_c);
    cudaGetSymbolAddress((void**)&pof,  d_ofeed);
    cudaGetSymbolAddress((void**)&pin0, d_inp0);
    cudaGetSymbolAddress((void**)&pg,   d_gpart);
    cudaGetSymbolAddress((void**)&pq,   d_qpart);
    cudaGetSymbolAddress((void**)&pp,   d_ppart);
    cudaGetSymbolAddress((void**)&patt, d_att);

    // state init (fresh every launch — deterministic)
    cudaMemcpyAsync(ph,  hid0, 2 * BB * HH * sizeof(float), cudaMemcpyDeviceToDevice, 0);
    cudaMemsetAsync(pc, 0,     2 * BB * HH * sizeof(float), 0);
    cudaMemcpyAsync(pof, out0, BB * EE * sizeof(float),     cudaMemcpyDeviceToDevice, 0);

    const long WL = (long)NGATE * 1024;   // per-layer weight size
    for (int t = 0; t < TT; t++) {
        prep_kernel<<<BB, 256>>>(tgt, emb, t);

        // LSTM layer 0: x = inp0, h = h[0]
        gemm256_kernel<<<dim3(16, KS_G), 256>>>(pin0, ph, Wih, Whh, 1024, NGATE, pg);
        cell_kernel<<<256, 256>>>(bih, bhh, ph, pc);

        // LSTM layer 1: x = h[0] (new), h = h[1]
        gemm256_kernel<<<dim3(16, KS_G), 256>>>(ph, ph + BB * HH,
                                                Wih + WL, Whh + WL, 1024, NGATE, pg);
        cell_kernel<<<256, 256>>>(bih + NGATE, bhh + NGATE, ph + BB * HH, pc + BB * HH);

        // q = h1 @ W1^T  (K=1024 entirely in region 0)
        gemm128_kernel<<<dim3(8, KS_Q), 256>>>(ph + BB * HH, ph + BB * HH, W1, W1,
                                               1024, VDIM, pq);
        // attention (q reduce + scores + softmax + attended)
        attn_kernel<<<BB, 256>>>(henc, b1);

        // out = tanh([attended, h1] @ W2^T + b2)
        gemm128_kernel<<<dim3(4, KS_P), 256>>>(patt, ph + BB * HH, W2, W2 + 1024,
                                               2048, EE, pp);
        projfinish_kernel<<<128, 256>>>(b2, out, t);
    }
}

// round 12
// speedup vs baseline: 1.0402x; 1.0402x over previous
#include <cuda_runtime.h>

// Problem constants
#define BB    64      // batch
#define TT    64      // timesteps
#define HH    1024    // hidden
#define EE    512     // embed
#define SS    128     // source len
#define VDIM  1024    // values size
#define NGATE 4096    // 4*H
#define KS_G  8       // gates K-splits   (chunk 256, K=2048)
#define KS_Q  16      // q     K-splits   (chunk 64,  K=1024)
#define KS_P  32      // proj  K-splits   (chunk 64,  K=2048)

// ---------- device scratch (static: no allocation allowed) ----------
__device__ float d_gpart[KS_G * BB * NGATE];   // 8 MB   gates partials [s][b][row]
__device__ float d_qpart[KS_Q * BB * VDIM];    // 4 MB   q partials
__device__ float d_ppart[KS_P * BB * EE];      // 4 MB   proj partials
__device__ float d_inp0 [BB * HH];             // layer0 input  = cat(embed, prev_output)
__device__ float d_h    [2 * BB * HH];         // LSTM hidden (both layers)
__device__ float d_c    [2 * BB * HH];         // LSTM cell
__device__ float d_att  [BB * VDIM];           // attended context

// ---------- packed f32x2 helpers (Blackwell FFMA2 path) ----------
__device__ __forceinline__ unsigned long long dup2(float x) {
    unsigned long long r;
    asm("mov.b64 %0, {%1, %1};" : "=l"(r) : "f"(x));
    return r;
}
__device__ __forceinline__ unsigned long long fma2(
    unsigned long long a, unsigned long long b, unsigned long long c) {
    unsigned long long d;
    asm("fma.rn.f32x2 %0, %1, %2, %3;" : "=l"(d) : "l"(a), "l"(b), "l"(c));
    return d;
}
__device__ __forceinline__ float2 unpack2(unsigned long long v) {
    float2 f;
    asm("mov.b64 {%0, %1}, %2;" : "=f"(f.x), "=f"(f.y) : "l"(v));
    return f;
}

// ---------- prep (t=0 only): inp0[b] = [emb[tgt[0,b]], output_init[b]] ----------
__global__ __launch_bounds__(256) void prep_kernel(
    const int* __restrict__ tgt, const float* __restrict__ emb,
    const float* __restrict__ out0)
{
    int b = blockIdx.x, tid = threadIdx.x;
    int tok = tgt[b];    // t = 0
    float4 v;
    if (tid < 128) v = ((const float4*)(emb + (long)tok * EE))[tid];
    else           v = ((const float4*)(out0 + b * EE))[tid - 128];
    ((float4*)(d_inp0 + b * HH))[tid] = v;
}

// ---------- split-K partial GEMM, 256 rows x 64 batch per block (FFMA2) ----------
// Cpart[ks][b][rowsTot] = sum_{k in chunk} W[row][k] * A[b][k]
// Thread tile: 16 rows (4 groups of 4, 64 apart) x 4 batch.
// Row pairs packed in f32x2 (natural from float4 W loads); batch operand dup'd.
__global__ __launch_bounds__(256) void gemm256_kernel(
    const float* __restrict__ A0, const float* __restrict__ A1,
    const float* __restrict__ W0, const float* __restrict__ W1,
    int strideW, int rowsTot, float* __restrict__ Cpart)
{
    __shared__ __align__(16) float Ws[16][256];
    __shared__ __align__(16) float As[16][64];

    const int row0  = blockIdx.x * 256;
    const int kbase = blockIdx.y * 256;          // 256 = KCHUNK
    const float* A = (kbase < 1024) ? A0 : A1;
    const float* W = (kbase < 1024) ? W0 : W1;
    const int kofs = (kbase < 1024) ? kbase : kbase - 1024;

    const int tid  = threadIdx.x;
    const int trow = tid & 15;          // row sub-group: rows 64q + 4*trow + {0..3}
    const int tcol = tid >> 4;          // batch group: cols tcol*4 + {0..3}
    const int lw_kq = tid & 3,  lw_r = tid >> 2;   // W loader
    const int la_b  = tid & 63, la_kq = tid >> 6;  // A loader

    unsigned long long acc2[8][4];      // [row-pair (q*2+p)][batch j]
    #pragma unroll
    for (int i = 0; i < 8; i++)
        #pragma unroll
        for (int j = 0; j < 4; j++) acc2[i][j] = 0ull;

    for (int kt = 0; kt < 16; kt++) {
        const int kk0 = kofs + kt * 16;
        // load W tile 256x16 (transposed into smem)
        #pragma unroll
        for (int i = 0; i < 4; i++) {
            int r = lw_r + 64 * i;
            float4 w4 = *(const float4*)&W[(long)(row0 + r) * strideW + kk0 + lw_kq * 4];
            Ws[lw_kq * 4 + 0][r] = w4.x; Ws[lw_kq * 4 + 1][r] = w4.y;
            Ws[lw_kq * 4 + 2][r] = w4.z; Ws[lw_kq * 4 + 3][r] = w4.w;
        }
        // load A tile 64x16
        {
            float4 a4 = *(const float4*)&A[la_b * 1024 + kk0 + la_kq * 4];
            As[la_kq * 4 + 0][la_b] = a4.x; As[la_kq * 4 + 1][la_b] = a4.y;
            As[la_kq * 4 + 2][la_b] = a4.z; As[la_kq * 4 + 3][la_b] = a4.w;
        }
        __syncthreads();
        #pragma unroll
        for (int kk = 0; kk < 16; kk++) {
            // W: 4 conflict-free LDS.128, each = 2 natural row pairs
            unsigned long long wp[8];
            #pragma unroll
            for (int q = 0; q < 4; q++) {
                ulonglong2 wq = *(const ulonglong2*)&Ws[kk][64 * q + trow * 4];
                wp[q * 2 + 0] = wq.x; wp[q * 2 + 1] = wq.y;
            }
            // A: one LDS.128, duplicate each batch value into both lanes
            float4 a4 = *(const float4*)&As[kk][tcol * 4];
            unsigned long long ad[4] = {dup2(a4.x), dup2(a4.y), dup2(a4.z), dup2(a4.w)};
            #pragma unroll
            for (int i = 0; i < 8; i++)
                #pragma unroll
                for (int j = 0; j < 4; j++)
                    acc2[i][j] = fma2(wp[i], ad[j], acc2[i][j]);
        }
        __syncthreads();
    }
    // store partials: [s][b][row]; row pair (2 consecutive) -> float2 store
    #pragma unroll
    for (int q = 0; q < 4; q++)
        #pragma unroll
        for (int p = 0; p < 2; p++) {
            int r = row0 + 64 * q + trow * 4 + 2 * p;
            #pragma unroll
            for (int j = 0; j < 4; j++) {
                int b = tcol * 4 + j;
                *(float2*)&Cpart[(long)(blockIdx.y * BB + b) * rowsTot + r] =
                    unpack2(acc2[q * 2 + p][j]);
            }
        }
}

// ---------- split-K partial GEMM, 128 rows x 64 batch, KCHUNK=64 (FFMA2) ----------
__global__ __launch_bounds__(256) void gemm128_kernel(
    const float* __restrict__ A0, const float* __restrict__ A1,
    const float* __restrict__ W0, const float* __restrict__ W1,
    int strideW, int rowsTot, float* __restrict__ Cpart)
{
    __shared__ __align__(16) float Ws[16][128];
    __shared__ __align__(16) float As[16][64];

    const int row0  = blockIdx.x * 128;
    const int kbase = blockIdx.y * 64;
    const float* A = (kbase < 1024) ? A0 : A1;
    const float* W = (kbase < 1024) ? W0 : W1;
    const int kofs = (kbase < 1024) ? kbase : kbase - 1024;

    const int tid  = threadIdx.x;
    const int trow = tid & 15;          // rows 64q + 4*trow + {0..3}, q in {0,1}
    const int tcol = tid >> 4;          // batch tcol*4 + {0..3}
    const int lw_kq = tid & 3,  lw_r = tid >> 2;
    const int la_b  = tid & 63, la_kq = tid >> 6;

    unsigned long long acc2[4][4];
    #pragma unroll
    for (int i = 0; i < 4; i++)
        #pragma unroll
        for (int j = 0; j < 4; j++) acc2[i][j] = 0ull;

    for (int kt = 0; kt < 4; kt++) {
        const int kk0 = kofs + kt * 16;
        #pragma unroll
        for (int i = 0; i < 2; i++) {
            int r = lw_r + 64 * i;
            float4 w4 = *(const float4*)&W[(long)(row0 + r) * strideW + kk0 + lw_kq * 4];
            Ws[lw_kq * 4 + 0][r] = w4.x; Ws[lw_kq * 4 + 1][r] = w4.y;
            Ws[lw_kq * 4 + 2][r] = w4.z; Ws[lw_kq * 4 + 3][r] = w4.w;
        }
        {
            float4 a4 = *(const float4*)&A[la_b * 1024 + kk0 + la_kq * 4];
            As[la_kq * 4 + 0][la_b] = a4.x; As[la_kq * 4 + 1][la_b] = a4.y;
            As[la_kq * 4 + 2][la_b] = a4.z; As[la_kq * 4 + 3][la_b] = a4.w;
        }
        __syncthreads();
        #pragma unroll
        for (int kk = 0; kk < 16; kk++) {
            unsigned long long wp[4];
            #pragma unroll
            for (int q = 0; q < 2; q++) {
                ulonglong2 wq = *(const ulonglong2*)&Ws[kk][64 * q + trow * 4];
                wp[q * 2 + 0] = wq.x; wp[q * 2 + 1] = wq.y;
            }
            float4 a4 = *(const float4*)&As[kk][tcol * 4];
            unsigned long long ad[4] = {dup2(a4.x), dup2(a4.y), dup2(a4.z), dup2(a4.w)};
            #pragma unroll
            for (int i = 0; i < 4; i++)
                #pragma unroll
                for (int j = 0; j < 4; j++)
                    acc2[i][j] = fma2(wp[i], ad[j], acc2[i][j]);
        }
        __syncthreads();
    }
    #pragma unroll
    for (int q = 0; q < 2; q++)
        #pragma unroll
        for (int p = 0; p < 2; p++) {
            int r = row0 + 64 * q + trow * 4 + 2 * p;
            #pragma unroll
            for (int j = 0; j < 4; j++) {
                int b = tcol * 4 + j;
                *(float2*)&Cpart[(long)(blockIdx.y * BB + b) * rowsTot + r] =
                    unpack2(acc2[q * 2 + p][j]);
            }
        }
}

// ---------- LSTM cell: reduce gate partials + bias + activations -> h,c (in place) ----------
__global__ __launch_bounds__(256) void cell_kernel(
    const float* __restrict__ bih, const float* __restrict__ bhh,
    float* __restrict__ h, float* __restrict__ c)
{
    int idx = blockIdx.x * 256 + threadIdx.x;   // 0..65535 = b*1024+hh
    int b = idx >> 10, hh = idx & 1023;
    float g[4];
    #pragma unroll
    for (int gi = 0; gi < 4; gi++) {
        int base = gi * 1024 + hh;
        float acc = bih[base] + bhh[base];
        #pragma unroll
        for (int s = 0; s < KS_G; s++) acc += d_gpart[(long)(s * BB + b) * NGATE + base];
        g[gi] = acc;
    }
    float i_ = 1.f / (1.f + expf(-g[0]));
    float f_ = 1.f / (1.f + expf(-g[1]));
    float gg = tanhf(g[2]);
    float o_ = 1.f / (1.f + expf(-g[3]));
    float cn = f_ * c[idx] + i_ * gg;
    c[idx] = cn;
    h[idx] = o_ * tanhf(cn);
}

// ---------- attention: reduce q partials, scores, softmax, attended (one block per b) ----------
__global__ __launch_bounds__(256) void attn_kernel(
    const float* __restrict__ henc, const float* __restrict__ b1)
{
    __shared__ __align__(16) float qv[VDIM];
    __shared__ float sc[SS];
    int b = blockIdx.x, tid = threadIdx.x;

    // reduce q partials + bias
    for (int v = tid; v < VDIM; v += 256) {
        float acc = b1[v];
        #pragma unroll
        for (int s = 0; s < KS_Q; s++) acc += d_qpart[(long)(s * BB + b) * VDIM + v];
        qv[v] = acc;
    }
    __syncthreads();

    // scores: 8 warps x 16 scores, warp-dot over V=1024
    int w = tid >> 5, l = tid & 31;
    const float4* hb = (const float4*)(henc + (long)b * SS * VDIM);
    const float4* q4 = (const float4*)qv;
    for (int i = 0; i < 16; i++) {
        int s = w * 16 + i;
        const float4* hr = hb + s * 256;
        float acc = 0.f;
        #pragma unroll
        for (int j = 0; j < 8; j++) {
            float4 qq = q4[l + j * 32];
            float4 hv = hr[l + j * 32];
            acc += qq.x * hv.x + qq.y * hv.y + qq.z * hv.z + qq.w * hv.w;
        }
        #pragma unroll
        for (int off = 16; off; off >>= 1) acc += __shfl_xor_sync(~0u, acc, off);
        if (l == 0) sc[s] = acc;
    }
    __syncthreads();

    // softmax over S=128 (warp 0)
    if (w == 0) {
        float v0 = sc[l], v1 = sc[l + 32], v2 = sc[l + 64], v3 = sc[l + 96];
        float m = fmaxf(fmaxf(v0, v1), fmaxf(v2, v3));
        #pragma unroll
        for (int off = 16; off; off >>= 1) m = fmaxf(m, __shfl_xor_sync(~0u, m, off));
        float e0 = expf(v0 - m), e1 = expf(v1 - m), e2 = expf(v2 - m), e3 = expf(v3 - m);
        float sum = e0 + e1 + e2 + e3;
        #pragma unroll
        for (int off = 16; off; off >>= 1) sum += __shfl_xor_sync(~0u, sum, off);
        float inv = 1.f / sum;
        sc[l] = e0 * inv; sc[l + 32] = e1 * inv; sc[l + 64] = e2 * inv; sc[l + 96] = e3 * inv;
    }
    __syncthreads();

    // attended = probs @ h_enc[b]
    float4 acc = {0.f, 0.f, 0.f, 0.f};
    #pragma unroll 4
    for (int s = 0; s < SS; s++) {
        float p = sc[s];
        float4 hv = hb[s * 256 + tid];
        acc.x += p * hv.x; acc.y += p * hv.y; acc.z += p * hv.z; acc.w += p * hv.w;
    }
    ((float4*)(d_att + b * VDIM))[tid] = acc;
}

// ---------- projection finish: reduce + bias + tanh, write output AND next-step inp0 ----------
// Also performs next step's prep: inp0[b] = [emb[tgt[t+1,b]], o]  (fuses prep_kernel)
__global__ __launch_bounds__(256) void projfinish_kernel(
    const float* __restrict__ b2, float* __restrict__ out,
    const int* __restrict__ tgt, const float* __restrict__ emb, int t)
{
    int idx = blockIdx.x * 256 + threadIdx.x;   // 0..32767 = b*512+e
    int b = idx >> 9, e = idx & 511;
    float acc = b2[e];
    #pragma unroll
    for (int s = 0; s < KS_P; s++) acc += d_ppart[(long)(s * BB + b) * EE + e];
    float o = tanhf(acc);
    out[(long)(b * TT + t) * EE + e] = o;
    if (t + 1 < TT) {
        // input-feed half for next step
        d_inp0[b * HH + EE + e] = o;
        // embedding half for next step
        int tok = tgt[(t + 1) * BB + b];
        d_inp0[b * HH + e] = emb[(long)tok * EE + e];
    }
}

// ---------- launcher ----------
extern "C" void kernel_launch(void* const* d_in, const int* in_sizes, int n_in,
                              void* d_out, int out_size)
{
    const int*   tgt  = (const int*)d_in[0];
    const float* henc = (const float*)d_in[1];
    const float* emb  = (const float*)d_in[2];
    const float* out0 = (const float*)d_in[3];
    const float* hid0 = (const float*)d_in[4];
    const float* Wih  = (const float*)d_in[5];
    const float* Whh  = (const float*)d_in[6];
    const float* bih  = (const float*)d_in[7];
    const float* bhh  = (const float*)d_in[8];
    const float* W1   = (const float*)d_in[9];
    const float* b1   = (const float*)d_in[10];
    const float* W2   = (const float*)d_in[11];
    const float* b2   = (const float*)d_in[12];
    float* out = (float*)d_out;

    float *ph, *pc, *pin0, *pg, *pq, *pp, *patt;
    cudaGetSymbolAddress((void**)&ph,   d_h);
    cudaGetSymbolAddress((void**)&pc,   d_c);
    cudaGetSymbolAddress((void**)&pin0, d_inp0);
    cudaGetSymbolAddress((void**)&pg,   d_gpart);
    cudaGetSymbolAddress((void**)&pq,   d_qpart);
    cudaGetSymbolAddress((void**)&pp,   d_ppart);
    cudaGetSymbolAddress((void**)&patt, d_att);

    // state init (fresh every launch — deterministic)
    cudaMemcpyAsync(ph,  hid0, 2 * BB * HH * sizeof(float), cudaMemcpyDeviceToDevice, 0);
    cudaMemsetAsync(pc, 0,     2 * BB * HH * sizeof(float), 0);

    // first-step input build (later steps fused into projfinish)
    prep_kernel<<<BB, 256>>>(tgt, emb, out0);

    const long WL = (long)NGATE * 1024;   // per-layer weight size
    for (int t = 0; t < TT; t++) {
        // LSTM layer 0: x = inp0, h = h[0]
        gemm256_kernel<<<dim3(16, KS_G), 256>>>(pin0, ph, Wih, Whh, 1024, NGATE, pg);
        cell_kernel<<<256, 256>>>(bih, bhh, ph, pc);

        // LSTM layer 1: x = h[0] (new), h = h[1]
        gemm256_kernel<<<dim3(16, KS_G), 256>>>(ph, ph + BB * HH,
                                                Wih + WL, Whh + WL, 1024, NGATE, pg);
        cell_kernel<<<256, 256>>>(bih + NGATE, bhh + NGATE, ph + BB * HH, pc + BB * HH);

        // q = h1 @ W1^T  (K=1024 entirely in region 0)
        gemm128_kernel<<<dim3(8, KS_Q), 256>>>(ph + BB * HH, ph + BB * HH, W1, W1,
                                               1024, VDIM, pq);
        // attention (q reduce + scores + softmax + attended)
        attn_kernel<<<BB, 256>>>(henc, b1);

        // out = tanh([attended, h1] @ W2^T + b2)
        gemm128_kernel<<<dim3(4, KS_P), 256>>>(patt, ph + BB * HH, W2, W2 + 1024,
                                               2048, EE, pp);
        projfinish_kernel<<<128, 256>>>(b2, out, tgt, emb, t);
    }
}